// round 7
// baseline (speedup 1.0000x reference)
#include <cuda_runtime.h>
#include <cuda_bf16.h>
#include <math.h>

#define T 2048
#define HID 7168
#define H 16
#define NOPE 128
#define ROPE 64
#define VD 128
#define QLR 1536
#define KVLR 512
#define IH 32
#define ID 128
#define TOPK 512

#define EPS 1e-6f
#define SCALE 0.07216878364870323f    // (192)^-0.5
#define ISCALE 0.08838834764831845f   // 128^-0.5
#define WSCALE 0.17677669529663687f   // 32^-0.5

// ---------------- scratch (device globals; no cudaMalloc allowed) ----------------
__device__ float g_cos[T * 32];
__device__ float g_sin[T * 32];
__device__ float g_qcn[T * QLR];
__device__ float g_kvn[T * KVLR];
__device__ float g_q[T * (H * (NOPE + ROPE))];      // T x 3072
__device__ float g_kv[T * (H * (NOPE + VD))];       // T x 4096
__device__ float g_kpe[T * ROPE];
__device__ float g_qidx[T * (IH * ID)];             // T x 4096
__device__ float g_kidxraw[T * ID];
__device__ float g_kidx[T * ID];
__device__ float g_widx[T * IH];
__device__ float g_scores[(size_t)T * T];
__device__ int   g_selidx[T * TOPK];
__device__ int   g_selcnt[T];
__device__ float g_obuf[T * (H * VD)];              // T x 2048

// ---------------- rope tables (correctly-rounded fp32 chain via double) ----------------
__global__ void rope_table_kernel(const int* __restrict__ pos) {
    int t = blockIdx.x, i = threadIdx.x;  // i in 0..31
    float e = (float)(2 * i) / 64.0f;                 // exact in fp32
    float p = (float)pow(10000.0, (double)e);         // ~correctly-rounded powf
    float inv = __fdiv_rn(1.0f, p);
    float ang = __fmul_rn((float)pos[t], inv);
    double ad = (double)ang;
    g_cos[t * 32 + i] = (float)cos(ad);               // ~correctly-rounded cosf
    g_sin[t * 32 + i] = (float)sin(ad);
}

// ---------------- rmsnorm (strict fp32 scale path) ----------------
__global__ void rmsnorm_kernel(const float* __restrict__ x, const float* __restrict__ w,
                               float* __restrict__ y, int D) {
    int t = blockIdx.x, tid = threadIdx.x;
    const float* xr = x + (size_t)t * D;
    float ss = 0.f;
    for (int i = tid; i < D; i += 256) { float v = xr[i]; ss += v * v; }
    __shared__ float red[256];
    red[tid] = ss; __syncthreads();
    for (int o = 128; o; o >>= 1) { if (tid < o) red[tid] += red[tid + o]; __syncthreads(); }
    float mean = __fdiv_rn(red[0], (float)D);
    float inv = __fdiv_rn(1.0f, __fsqrt_rn(__fadd_rn(mean, EPS)));
    float* yr = y + (size_t)t * D;
    for (int i = tid; i < D; i += 256)
        yr[i] = __fmul_rn(__fmul_rn(xr[i], inv), w[i]);
}

// ---------------- SGEMM: double-buffered, k-ascending FMA chain per output ----------------
__global__ __launch_bounds__(256) void sgemm_kernel(
    const float* __restrict__ A, const float* __restrict__ B, float* __restrict__ C,
    int M, int N, int K, float scale) {
    __shared__ float As[2][8][128];
    __shared__ float Bs[2][8][128];
    int bm = blockIdx.y * 128, bn = blockIdx.x * 128;
    int tid = threadIdx.x;
    int am = tid >> 1, ak = (tid & 1) * 4;
    int bk = tid >> 5, bn4 = (tid & 31) * 4;
    int tx = tid & 15, ty = tid >> 4;
    float acc[8][8];
#pragma unroll
    for (int i = 0; i < 8; i++)
#pragma unroll
        for (int j = 0; j < 8; j++) acc[i][j] = 0.f;

    const float* Abase = A + (size_t)(bm + am) * K + ak;
    const float* Bbase = B + (size_t)bk * N + bn + bn4;

    {
        float4 av = *(const float4*)(Abase);
        As[0][ak + 0][am] = av.x; As[0][ak + 1][am] = av.y;
        As[0][ak + 2][am] = av.z; As[0][ak + 3][am] = av.w;
        *(float4*)&Bs[0][bk][bn4] = *(const float4*)(Bbase);
    }
    __syncthreads();

    int kIters = K >> 3;
    int cur = 0;
    for (int it = 0; it < kIters; it++) {
        float4 av, bv;
        bool more = (it + 1 < kIters);
        if (more) {
            av = *(const float4*)(Abase + (it + 1) * 8);
            bv = *(const float4*)(Bbase + (size_t)(it + 1) * 8 * N);
        }
#pragma unroll
        for (int kk = 0; kk < 8; kk++) {
            float a[8], b[8];
            *(float4*)(a)     = *(float4*)&As[cur][kk][ty * 4];
            *(float4*)(a + 4) = *(float4*)&As[cur][kk][64 + ty * 4];
            *(float4*)(b)     = *(float4*)&Bs[cur][kk][tx * 4];
            *(float4*)(b + 4) = *(float4*)&Bs[cur][kk][64 + tx * 4];
#pragma unroll
            for (int i = 0; i < 8; i++)
#pragma unroll
                for (int j = 0; j < 8; j++)
                    acc[i][j] = __fmaf_rn(a[i], b[j], acc[i][j]);
        }
        if (more) {
            int nxt = cur ^ 1;
            As[nxt][ak + 0][am] = av.x; As[nxt][ak + 1][am] = av.y;
            As[nxt][ak + 2][am] = av.z; As[nxt][ak + 3][am] = av.w;
            *(float4*)&Bs[nxt][bk][bn4] = bv;
            __syncthreads();
            cur = nxt;
        }
    }
#pragma unroll
    for (int i = 0; i < 8; i++) {
        int m = bm + ((i < 4) ? (ty * 4 + i) : (64 + ty * 4 + i - 4));
#pragma unroll
        for (int jb = 0; jb < 2; jb++) {
            int n = bn + ((jb == 0) ? (tx * 4) : (64 + tx * 4));
            float4 v;
            v.x = __fmul_rn(acc[i][jb * 4 + 0], scale);
            v.y = __fmul_rn(acc[i][jb * 4 + 1], scale);
            v.z = __fmul_rn(acc[i][jb * 4 + 2], scale);
            v.w = __fmul_rn(acc[i][jb * 4 + 3], scale);
            *(float4*)(C + (size_t)m * N + n) = v;
        }
    }
}

// ---------------- skinny SGEMM for tall-thin C (N<=128): M-tile 8, k-chunk 32 ----------------
__global__ __launch_bounds__(256) void skinny_sgemm_kernel(
    const float* __restrict__ A, const float* __restrict__ B, float* __restrict__ C,
    int M, int N, int K, float scale) {
    __shared__ float As[32][9];
    __shared__ float Bs[32][128];
    int bm = blockIdx.y * 8;
    int tid = threadIdx.x;
    int ncol4 = N >> 2;
    int nout = 8 * ncol4;
    int row = tid / ncol4;
    int c4 = tid % ncol4;
    bool active = tid < nout;

    float acc0 = 0.f, acc1 = 0.f, acc2 = 0.f, acc3 = 0.f;
    int arow = tid >> 5, akk = tid & 31;
    const float* Aload = A + (size_t)(bm + arow) * K + akk;
    int totalf4 = 32 * ncol4;

    for (int k0 = 0; k0 < K; k0 += 32) {
        As[akk][arow] = Aload[k0];
#pragma unroll
        for (int i = 0; i < 4; i++) {
            int idx = tid + 256 * i;
            if (idx < totalf4) {
                int kk = idx / ncol4, cc = idx % ncol4;
                *(float4*)&Bs[kk][cc * 4] =
                    *(const float4*)(B + (size_t)(k0 + kk) * N + cc * 4);
            }
        }
        __syncthreads();
        if (active) {
#pragma unroll
            for (int kk = 0; kk < 32; kk++) {
                float a = As[kk][row];
                float4 b = *(float4*)&Bs[kk][c4 * 4];
                acc0 = __fmaf_rn(a, b.x, acc0);
                acc1 = __fmaf_rn(a, b.y, acc1);
                acc2 = __fmaf_rn(a, b.z, acc2);
                acc3 = __fmaf_rn(a, b.w, acc3);
            }
        }
        __syncthreads();
    }
    if (active) {
        float4 v;
        v.x = __fmul_rn(acc0, scale);
        v.y = __fmul_rn(acc1, scale);
        v.z = __fmul_rn(acc2, scale);
        v.w = __fmul_rn(acc3, scale);
        *(float4*)(C + (size_t)(bm + row) * N + c4 * 4) = v;
    }
}

// ---------------- rope (interleaved) on q_pe, strict rounding ----------------
__global__ void rope_q_kernel() {
    int th = blockIdx.x;
    int t = th / H, h = th % H;
    int i = threadIdx.x;  // 0..31
    float c = g_cos[t * 32 + i], s = g_sin[t * 32 + i];
    float* p = g_q + (size_t)t * 3072 + h * 192 + 128 + 2 * i;
    float xe = p[0], xo = p[1];
    p[0] = __fsub_rn(__fmul_rn(xe, c), __fmul_rn(xo, s));
    p[1] = __fadd_rn(__fmul_rn(xo, c), __fmul_rn(xe, s));
}

// ---------------- rope (interleaved) on k_pe -> g_kpe ----------------
__global__ void rope_kpe_kernel(const float* __restrict__ k_pe) {
    int t = blockIdx.x;
    int i = threadIdx.x;  // 0..31
    float c = g_cos[t * 32 + i], s = g_sin[t * 32 + i];
    const float* p = k_pe + (size_t)t * 64 + 2 * i;
    float xe = p[0], xo = p[1];
    g_kpe[t * 64 + 2 * i]     = __fsub_rn(__fmul_rn(xe, c), __fmul_rn(xo, s));
    g_kpe[t * 64 + 2 * i + 1] = __fadd_rn(__fmul_rn(xo, c), __fmul_rn(xe, s));
}

// ---------------- rope (neox) on q_idx first 64 dims, in-place ----------------
__global__ void rope_qidx_kernel() {
    int tih = blockIdx.x;
    int t = tih / IH, ih = tih % IH;
    int i = threadIdx.x;  // 0..31
    float c = g_cos[t * 32 + i], s = g_sin[t * 32 + i];
    float* p = g_qidx + (size_t)t * 4096 + ih * 128;
    float x1 = p[i], x2 = p[32 + i];
    p[i]      = __fsub_rn(__fmul_rn(x1, c), __fmul_rn(x2, s));
    p[32 + i] = __fadd_rn(__fmul_rn(x2, c), __fmul_rn(x1, s));
}

// ---------------- k_idx: layernorm + neox rope, strict rounding ----------------
__global__ void kidx_kernel(const float* __restrict__ gamma, const float* __restrict__ beta) {
    int t = blockIdx.x, tid = threadIdx.x;  // 128 threads
    __shared__ float x[128];
    __shared__ float red[128];
    float v = g_kidxraw[(size_t)t * 128 + tid];
    red[tid] = v; __syncthreads();
    for (int o = 64; o; o >>= 1) { if (tid < o) red[tid] += red[tid + o]; __syncthreads(); }
    float mu = __fdiv_rn(red[0], 128.f); __syncthreads();
    float d = __fsub_rn(v, mu);
    red[tid] = __fmul_rn(d, d); __syncthreads();
    for (int o = 64; o; o >>= 1) { if (tid < o) red[tid] += red[tid + o]; __syncthreads(); }
    float var = __fdiv_rn(red[0], 128.f);
    float inv = __fdiv_rn(1.0f, __fsqrt_rn(__fadd_rn(var, EPS)));
    x[tid] = __fadd_rn(__fmul_rn(__fmul_rn(d, inv), gamma[tid]), beta[tid]);
    __syncthreads();
    if (tid < 32) {
        float c = g_cos[t * 32 + tid], s = g_sin[t * 32 + tid];
        float x1 = x[tid], x2 = x[tid + 32];
        g_kidx[(size_t)t * 128 + tid]      = __fsub_rn(__fmul_rn(x1, c), __fmul_rn(x2, s));
        g_kidx[(size_t)t * 128 + tid + 32] = __fadd_rn(__fmul_rn(x2, c), __fmul_rn(x1, s));
    } else if (tid >= 64) {
        g_kidx[(size_t)t * 128 + tid] = x[tid];
    }
}

// ---------------- indexer scores: grid (4 slices, T rows), longest rows first ----------------
#define SC_SLICES 4
__global__ __launch_bounds__(256) void scores_kernel() {
    int t = (T - 1) - blockIdx.y;
    int slice = blockIdx.x;
    __shared__ float qs[32 * 129];
    __shared__ float ks[32 * 129];
    __shared__ float ws[32];
    __shared__ float lg[32][33];
    int tid = threadIdx.x;
    for (int i = tid; i < 4096; i += 256) {
        int hh = i >> 7, dd = i & 127;
        qs[hh * 129 + dd] = g_qidx[(size_t)t * 4096 + i];
    }
    if (tid < 32) ws[tid] = g_widx[t * 32 + tid];
    int ntile = t / 32 + 1;
    int jl = (tid & 15) * 2;
    int hl = (tid >> 4) * 2;
    for (int jt = slice; jt < ntile; jt += SC_SLICES) {
        int jbase = jt * 32;
        __syncthreads();
        for (int i = tid; i < 4096; i += 256) {
            int jj = i >> 7, dd = i & 127;
            ks[jj * 129 + dd] = g_kidx[(size_t)jbase * 128 + i];
        }
        __syncthreads();
        float a00 = 0.f, a01 = 0.f, a10 = 0.f, a11 = 0.f;
        const float* q0 = &qs[hl * 129];
        const float* q1 = &qs[(hl + 1) * 129];
        const float* k0 = &ks[jl * 129];
        const float* k1 = &ks[(jl + 1) * 129];
#pragma unroll 8
        for (int d = 0; d < 128; d++) {
            float kv0 = k0[d], kv1 = k1[d];
            float qv0 = q0[d], qv1 = q1[d];
            a00 = __fmaf_rn(qv0, kv0, a00); a01 = __fmaf_rn(qv0, kv1, a01);
            a10 = __fmaf_rn(qv1, kv0, a10); a11 = __fmaf_rn(qv1, kv1, a11);
        }
        lg[hl][jl]         = fmaxf(__fmul_rn(a00, ISCALE), 0.f);
        lg[hl][jl + 1]     = fmaxf(__fmul_rn(a01, ISCALE), 0.f);
        lg[hl + 1][jl]     = fmaxf(__fmul_rn(a10, ISCALE), 0.f);
        lg[hl + 1][jl + 1] = fmaxf(__fmul_rn(a11, ISCALE), 0.f);
        __syncthreads();
        if (tid < 32) {
            int j = jbase + tid;
            float s = 0.f;
#pragma unroll
            for (int h = 0; h < 32; h++)
                s = __fmaf_rn(ws[h], lg[h][tid], s);
            g_scores[(size_t)t * T + j] = (j <= t) ? s : -INFINITY;
        }
    }
    for (int j = ntile * 32 + slice * 256 + tid; j < T; j += SC_SLICES * 256)
        g_scores[(size_t)t * T + j] = -INFINITY;
}

// ---------------- per-row top-512: quick path for t<=510, bitonic sort otherwise ----------------
__global__ __launch_bounds__(1024) void topk_kernel() {
    int t = blockIdx.x, tid = threadIdx.x;
    if (t <= TOPK - 2) {
        // all causal keys are selected (t+1 finite scores <= 512);
        // -inf picks beyond t are masked by & causal in the reference.
        int cnt = t + 1;
        if (tid == 0) g_selcnt[t] = cnt;
        for (int k = tid; k < cnt; k += 1024) g_selidx[t * TOPK + k] = k;
        return;
    }
    __shared__ unsigned long long keys[2048];
    for (int i = tid; i < 2048; i += 1024) {
        float s = g_scores[(size_t)t * T + i];
        unsigned u = __float_as_uint(s);
        u = (u & 0x80000000u) ? ~u : (u | 0x80000000u);
        keys[i] = ((unsigned long long)u << 32) | (unsigned)(2047 - i);
    }
    __syncthreads();
    for (int k = 2; k <= 2048; k <<= 1) {
        for (int j = k >> 1; j > 0; j >>= 1) {
            for (int i = tid; i < 2048; i += 1024) {
                int ixj = i ^ j;
                if (ixj > i) {
                    unsigned long long a = keys[i], b = keys[ixj];
                    bool desc = ((i & k) == 0);
                    if (desc ? (a < b) : (a > b)) { keys[i] = b; keys[ixj] = a; }
                }
            }
            __syncthreads();
        }
    }
    if (tid == 0) g_selcnt[t] = TOPK;
    if (tid < TOPK) {
        g_selidx[t * TOPK + tid] = 2047 - (int)(keys[tid] & 0xFFFFFFFFu);
    }
}

// ---------------- gathered sparse attention: one block per t, warp per head ----------------
__global__ __launch_bounds__(512) void attn_kernel() {
    int t = blockIdx.x;
    int tid = threadIdx.x;
    int wid = tid >> 5, lane = tid & 31;   // wid = head
    __shared__ float qs[3072];
    __shared__ int   sel[TOPK];
    __shared__ float lg[16][TOPK];
    int cnt = g_selcnt[t];
    for (int i = tid; i < 3072; i += 512) qs[i] = g_q[(size_t)t * 3072 + i];
    for (int k = tid; k < cnt; k += 512) sel[k] = g_selidx[t * TOPK + k];
    __syncthreads();

    const float* qn = &qs[wid * 192];
    const float* qp = &qs[wid * 192 + 128];

    // logits: lane handles keys lane, lane+32, ... (two separate d-ascending dots)
    for (int kk = lane; kk < cnt; kk += 32) {
        int j = sel[kk];
        const float4* kn4 = (const float4*)(g_kv + (size_t)j * 4096 + wid * 256);
        float s1 = 0.f;
#pragma unroll
        for (int d4 = 0; d4 < 32; d4++) {
            float4 kv = kn4[d4];
            s1 = __fmaf_rn(qn[4 * d4 + 0], kv.x, s1);
            s1 = __fmaf_rn(qn[4 * d4 + 1], kv.y, s1);
            s1 = __fmaf_rn(qn[4 * d4 + 2], kv.z, s1);
            s1 = __fmaf_rn(qn[4 * d4 + 3], kv.w, s1);
        }
        const float4* kp4 = (const float4*)(g_kpe + (size_t)j * 64);
        float s2 = 0.f;
#pragma unroll
        for (int d4 = 0; d4 < 16; d4++) {
            float4 kv = kp4[d4];
            s2 = __fmaf_rn(qp[4 * d4 + 0], kv.x, s2);
            s2 = __fmaf_rn(qp[4 * d4 + 1], kv.y, s2);
            s2 = __fmaf_rn(qp[4 * d4 + 2], kv.z, s2);
            s2 = __fmaf_rn(qp[4 * d4 + 3], kv.w, s2);
        }
        lg[wid][kk] = __fmul_rn(__fadd_rn(s1, s2), SCALE);
    }
    __syncwarp();

    // per-head softmax via warp reductions (continuous path)
    float m = -INFINITY;
    for (int kk = lane; kk < cnt; kk += 32) m = fmaxf(m, lg[wid][kk]);
#pragma unroll
    for (int o = 16; o; o >>= 1) m = fmaxf(m, __shfl_xor_sync(0xffffffffu, m, o));
    float sum = 0.f;
    for (int kk = lane; kk < cnt; kk += 32) {
        float p = (float)exp((double)__fsub_rn(lg[wid][kk], m));
        lg[wid][kk] = p;
        sum += p;
    }
#pragma unroll
    for (int o = 16; o; o >>= 1) sum += __shfl_xor_sync(0xffffffffu, sum, o);
    __syncwarp();
    for (int kk = lane; kk < cnt; kk += 32) lg[wid][kk] = __fdiv_rn(lg[wid][kk], sum);
    __syncwarp();

    // pv: k-ascending (sel-order) FMA chain per output element, matching R6
    float a0 = 0.f, a1 = 0.f, a2 = 0.f, a3 = 0.f;
    for (int k = 0; k < cnt; k++) {
        int j = sel[k];
        float p = lg[wid][k];
        const float* v = g_kv + (size_t)j * 4096 + wid * 256 + 128;
        a0 = __fmaf_rn(p, v[lane], a0);
        a1 = __fmaf_rn(p, v[lane + 32], a1);
        a2 = __fmaf_rn(p, v[lane + 64], a2);
        a3 = __fmaf_rn(p, v[lane + 96], a3);
    }
    float* o = g_obuf + (size_t)t * 2048 + wid * 128;
    o[lane]      = a0;
    o[lane + 32] = a1;
    o[lane + 64] = a2;
    o[lane + 96] = a3;
}

// ---------------- launch ----------------
extern "C" void kernel_launch(void* const* d_in, const int* in_sizes, int n_in,
                              void* d_out, int out_size) {
    const int*   positions = (const int*)d_in[0];
    const float* hidden    = (const float*)d_in[1];
    const float* q_c       = (const float*)d_in[2];
    const float* kv_c      = (const float*)d_in[3];
    const float* k_pe      = (const float*)d_in[4];
    const float* q_a_ln_w  = (const float*)d_in[5];
    const float* kv_a_ln_w = (const float*)d_in[6];
    const float* Wq_b      = (const float*)d_in[7];
    const float* Wkv_b     = (const float*)d_in[8];
    const float* Wo        = (const float*)d_in[9];
    const float* Wiq       = (const float*)d_in[10];
    const float* Wik       = (const float*)d_in[11];
    const float* ik_gamma  = (const float*)d_in[12];
    const float* ik_beta   = (const float*)d_in[13];
    const float* Ww        = (const float*)d_in[14];
    float* out = (float*)d_out;

    float* p_qcn;     cudaGetSymbolAddress((void**)&p_qcn, g_qcn);
    float* p_kvn;     cudaGetSymbolAddress((void**)&p_kvn, g_kvn);
    float* p_q;       cudaGetSymbolAddress((void**)&p_q, g_q);
    float* p_kv;      cudaGetSymbolAddress((void**)&p_kv, g_kv);
    float* p_qidx;    cudaGetSymbolAddress((void**)&p_qidx, g_qidx);
    float* p_kidxraw; cudaGetSymbolAddress((void**)&p_kidxraw, g_kidxraw);
    float* p_widx;    cudaGetSymbolAddress((void**)&p_widx, g_widx);
    float* p_obuf;    cudaGetSymbolAddress((void**)&p_obuf, g_obuf);

    rope_table_kernel<<<T, 32>>>(positions);
    rmsnorm_kernel<<<T, 256>>>(q_c, q_a_ln_w, p_qcn, QLR);
    rmsnorm_kernel<<<T, 256>>>(kv_c, kv_a_ln_w, p_kvn, KVLR);

    sgemm_kernel<<<dim3(3072 / 128, T / 128), 256>>>(p_qcn, Wq_b, p_q, T, 3072, QLR, 1.f);
    sgemm_kernel<<<dim3(4096 / 128, T / 128), 256>>>(p_kvn, Wkv_b, p_kv, T, 4096, KVLR, 1.f);
    sgemm_kernel<<<dim3(4096 / 128, T / 128), 256>>>(p_qcn, Wiq, p_qidx, T, 4096, QLR, 1.f);
    skinny_sgemm_kernel<<<dim3(1, T / 8), 256>>>(hidden, Wik, p_kidxraw, T, 128, HID, 1.f);
    skinny_sgemm_kernel<<<dim3(1, T / 8), 256>>>(hidden, Ww, p_widx, T, 32, HID, WSCALE);

    rope_q_kernel<<<T * H, 32>>>();
    rope_kpe_kernel<<<T, 32>>>(k_pe);
    rope_qidx_kernel<<<T * IH, 32>>>();
    kidx_kernel<<<T, 128>>>(ik_gamma, ik_beta);

    scores_kernel<<<dim3(SC_SLICES, T), 256>>>();
    topk_kernel<<<T, 1024>>>();
    attn_kernel<<<T, 512>>>();

    sgemm_kernel<<<dim3(HID / 128, T / 128), 256>>>(p_obuf, Wo, out, T, HID, 2048, 1.f);
}

// round 8
// speedup vs baseline: 1.5399x; 1.5399x over previous
#include <cuda_runtime.h>
#include <cuda_bf16.h>
#include <math.h>

#define T 2048
#define HID 7168
#define H 16
#define NOPE 128
#define ROPE 64
#define VD 128
#define QLR 1536
#define KVLR 512
#define IH 32
#define ID 128
#define TOPK 512

#define EPS 1e-6f
#define SCALE 0.07216878364870323f    // (192)^-0.5
#define ISCALE 0.08838834764831845f   // 128^-0.5
#define WSCALE 0.17677669529663687f   // 32^-0.5

// ---------------- scratch (device globals; no cudaMalloc allowed) ----------------
__device__ float g_cos[T * 32];
__device__ float g_sin[T * 32];
__device__ float g_qcn[T * QLR];
__device__ float g_kvn[T * KVLR];
__device__ float g_q[T * (H * (NOPE + ROPE))];      // T x 3072
__device__ float g_kv[T * (H * (NOPE + VD))];       // T x 4096
__device__ float g_kpe[T * ROPE];
__device__ float g_qidx[T * (IH * ID)];             // T x 4096
__device__ float g_kidxraw[T * ID];
__device__ float g_kidx[T * ID];
__device__ float g_widx[T * IH];
__device__ float g_scores[(size_t)T * T];
__device__ int   g_selidx[T * TOPK];
__device__ int   g_selcnt[T];
__device__ float g_obuf[T * (H * VD)];              // T x 2048

// ---------------- rope tables (correctly-rounded fp32 chain via double) ----------------
__global__ void rope_table_kernel(const int* __restrict__ pos) {
    int t = blockIdx.x, i = threadIdx.x;  // i in 0..31
    float e = (float)(2 * i) / 64.0f;                 // exact in fp32
    float p = (float)pow(10000.0, (double)e);         // ~correctly-rounded powf
    float inv = __fdiv_rn(1.0f, p);
    float ang = __fmul_rn((float)pos[t], inv);
    double ad = (double)ang;
    g_cos[t * 32 + i] = (float)cos(ad);               // ~correctly-rounded cosf
    g_sin[t * 32 + i] = (float)sin(ad);
}

// ---------------- rmsnorm (strict fp32 scale path) ----------------
__global__ void rmsnorm_kernel(const float* __restrict__ x, const float* __restrict__ w,
                               float* __restrict__ y, int D) {
    int t = blockIdx.x, tid = threadIdx.x;
    const float* xr = x + (size_t)t * D;
    float ss = 0.f;
    for (int i = tid; i < D; i += 256) { float v = xr[i]; ss += v * v; }
    __shared__ float red[256];
    red[tid] = ss; __syncthreads();
    for (int o = 128; o; o >>= 1) { if (tid < o) red[tid] += red[tid + o]; __syncthreads(); }
    float mean = __fdiv_rn(red[0], (float)D);
    float inv = __fdiv_rn(1.0f, __fsqrt_rn(__fadd_rn(mean, EPS)));
    float* yr = y + (size_t)t * D;
    for (int i = tid; i < D; i += 256)
        yr[i] = __fmul_rn(__fmul_rn(xr[i], inv), w[i]);
}

// ---------------- SGEMM: double-buffered, k-ascending FMA chain per output ----------------
__global__ __launch_bounds__(256) void sgemm_kernel(
    const float* __restrict__ A, const float* __restrict__ B, float* __restrict__ C,
    int M, int N, int K, float scale) {
    __shared__ float As[2][8][128];
    __shared__ float Bs[2][8][128];
    int bm = blockIdx.y * 128, bn = blockIdx.x * 128;
    int tid = threadIdx.x;
    int am = tid >> 1, ak = (tid & 1) * 4;
    int bk = tid >> 5, bn4 = (tid & 31) * 4;
    int tx = tid & 15, ty = tid >> 4;
    float acc[8][8];
#pragma unroll
    for (int i = 0; i < 8; i++)
#pragma unroll
        for (int j = 0; j < 8; j++) acc[i][j] = 0.f;

    const float* Abase = A + (size_t)(bm + am) * K + ak;
    const float* Bbase = B + (size_t)bk * N + bn + bn4;

    {
        float4 av = *(const float4*)(Abase);
        As[0][ak + 0][am] = av.x; As[0][ak + 1][am] = av.y;
        As[0][ak + 2][am] = av.z; As[0][ak + 3][am] = av.w;
        *(float4*)&Bs[0][bk][bn4] = *(const float4*)(Bbase);
    }
    __syncthreads();

    int kIters = K >> 3;
    int cur = 0;
    for (int it = 0; it < kIters; it++) {
        float4 av, bv;
        bool more = (it + 1 < kIters);
        if (more) {
            av = *(const float4*)(Abase + (it + 1) * 8);
            bv = *(const float4*)(Bbase + (size_t)(it + 1) * 8 * N);
        }
#pragma unroll
        for (int kk = 0; kk < 8; kk++) {
            float a[8], b[8];
            *(float4*)(a)     = *(float4*)&As[cur][kk][ty * 4];
            *(float4*)(a + 4) = *(float4*)&As[cur][kk][64 + ty * 4];
            *(float4*)(b)     = *(float4*)&Bs[cur][kk][tx * 4];
            *(float4*)(b + 4) = *(float4*)&Bs[cur][kk][64 + tx * 4];
#pragma unroll
            for (int i = 0; i < 8; i++)
#pragma unroll
                for (int j = 0; j < 8; j++)
                    acc[i][j] = __fmaf_rn(a[i], b[j], acc[i][j]);
        }
        if (more) {
            int nxt = cur ^ 1;
            As[nxt][ak + 0][am] = av.x; As[nxt][ak + 1][am] = av.y;
            As[nxt][ak + 2][am] = av.z; As[nxt][ak + 3][am] = av.w;
            *(float4*)&Bs[nxt][bk][bn4] = bv;
            __syncthreads();
            cur = nxt;
        }
    }
#pragma unroll
    for (int i = 0; i < 8; i++) {
        int m = bm + ((i < 4) ? (ty * 4 + i) : (64 + ty * 4 + i - 4));
#pragma unroll
        for (int jb = 0; jb < 2; jb++) {
            int n = bn + ((jb == 0) ? (tx * 4) : (64 + tx * 4));
            float4 v;
            v.x = __fmul_rn(acc[i][jb * 4 + 0], scale);
            v.y = __fmul_rn(acc[i][jb * 4 + 1], scale);
            v.z = __fmul_rn(acc[i][jb * 4 + 2], scale);
            v.w = __fmul_rn(acc[i][jb * 4 + 3], scale);
            *(float4*)(C + (size_t)m * N + n) = v;
        }
    }
}

// ---------------- skinny SGEMM for tall-thin C (N<=128): M-tile 8, k-chunk 32 ----------------
__global__ __launch_bounds__(256) void skinny_sgemm_kernel(
    const float* __restrict__ A, const float* __restrict__ B, float* __restrict__ C,
    int M, int N, int K, float scale) {
    __shared__ float As[32][9];
    __shared__ float Bs[32][128];
    int bm = blockIdx.y * 8;
    int tid = threadIdx.x;
    int ncol4 = N >> 2;
    int nout = 8 * ncol4;
    int row = tid / ncol4;
    int c4 = tid % ncol4;
    bool active = tid < nout;

    float acc0 = 0.f, acc1 = 0.f, acc2 = 0.f, acc3 = 0.f;
    int arow = tid >> 5, akk = tid & 31;
    const float* Aload = A + (size_t)(bm + arow) * K + akk;
    int totalf4 = 32 * ncol4;

    for (int k0 = 0; k0 < K; k0 += 32) {
        As[akk][arow] = Aload[k0];
#pragma unroll
        for (int i = 0; i < 4; i++) {
            int idx = tid + 256 * i;
            if (idx < totalf4) {
                int kk = idx / ncol4, cc = idx % ncol4;
                *(float4*)&Bs[kk][cc * 4] =
                    *(const float4*)(B + (size_t)(k0 + kk) * N + cc * 4);
            }
        }
        __syncthreads();
        if (active) {
#pragma unroll
            for (int kk = 0; kk < 32; kk++) {
                float a = As[kk][row];
                float4 b = *(float4*)&Bs[kk][c4 * 4];
                acc0 = __fmaf_rn(a, b.x, acc0);
                acc1 = __fmaf_rn(a, b.y, acc1);
                acc2 = __fmaf_rn(a, b.z, acc2);
                acc3 = __fmaf_rn(a, b.w, acc3);
            }
        }
        __syncthreads();
    }
    if (active) {
        float4 v;
        v.x = __fmul_rn(acc0, scale);
        v.y = __fmul_rn(acc1, scale);
        v.z = __fmul_rn(acc2, scale);
        v.w = __fmul_rn(acc3, scale);
        *(float4*)(C + (size_t)(bm + row) * N + c4 * 4) = v;
    }
}

// ---------------- rope (interleaved) on q_pe, strict rounding ----------------
__global__ void rope_q_kernel() {
    int th = blockIdx.x;
    int t = th / H, h = th % H;
    int i = threadIdx.x;  // 0..31
    float c = g_cos[t * 32 + i], s = g_sin[t * 32 + i];
    float* p = g_q + (size_t)t * 3072 + h * 192 + 128 + 2 * i;
    float xe = p[0], xo = p[1];
    p[0] = __fsub_rn(__fmul_rn(xe, c), __fmul_rn(xo, s));
    p[1] = __fadd_rn(__fmul_rn(xo, c), __fmul_rn(xe, s));
}

// ---------------- rope (interleaved) on k_pe -> g_kpe ----------------
__global__ void rope_kpe_kernel(const float* __restrict__ k_pe) {
    int t = blockIdx.x;
    int i = threadIdx.x;  // 0..31
    float c = g_cos[t * 32 + i], s = g_sin[t * 32 + i];
    const float* p = k_pe + (size_t)t * 64 + 2 * i;
    float xe = p[0], xo = p[1];
    g_kpe[t * 64 + 2 * i]     = __fsub_rn(__fmul_rn(xe, c), __fmul_rn(xo, s));
    g_kpe[t * 64 + 2 * i + 1] = __fadd_rn(__fmul_rn(xo, c), __fmul_rn(xe, s));
}

// ---------------- rope (neox) on q_idx first 64 dims, in-place ----------------
__global__ void rope_qidx_kernel() {
    int tih = blockIdx.x;
    int t = tih / IH, ih = tih % IH;
    int i = threadIdx.x;  // 0..31
    float c = g_cos[t * 32 + i], s = g_sin[t * 32 + i];
    float* p = g_qidx + (size_t)t * 4096 + ih * 128;
    float x1 = p[i], x2 = p[32 + i];
    p[i]      = __fsub_rn(__fmul_rn(x1, c), __fmul_rn(x2, s));
    p[32 + i] = __fadd_rn(__fmul_rn(x2, c), __fmul_rn(x1, s));
}

// ---------------- k_idx: layernorm + neox rope, strict rounding ----------------
__global__ void kidx_kernel(const float* __restrict__ gamma, const float* __restrict__ beta) {
    int t = blockIdx.x, tid = threadIdx.x;  // 128 threads
    __shared__ float x[128];
    __shared__ float red[128];
    float v = g_kidxraw[(size_t)t * 128 + tid];
    red[tid] = v; __syncthreads();
    for (int o = 64; o; o >>= 1) { if (tid < o) red[tid] += red[tid + o]; __syncthreads(); }
    float mu = __fdiv_rn(red[0], 128.f); __syncthreads();
    float d = __fsub_rn(v, mu);
    red[tid] = __fmul_rn(d, d); __syncthreads();
    for (int o = 64; o; o >>= 1) { if (tid < o) red[tid] += red[tid + o]; __syncthreads(); }
    float var = __fdiv_rn(red[0], 128.f);
    float inv = __fdiv_rn(1.0f, __fsqrt_rn(__fadd_rn(var, EPS)));
    x[tid] = __fadd_rn(__fmul_rn(__fmul_rn(d, inv), gamma[tid]), beta[tid]);
    __syncthreads();
    if (tid < 32) {
        float c = g_cos[t * 32 + tid], s = g_sin[t * 32 + tid];
        float x1 = x[tid], x2 = x[tid + 32];
        g_kidx[(size_t)t * 128 + tid]      = __fsub_rn(__fmul_rn(x1, c), __fmul_rn(x2, s));
        g_kidx[(size_t)t * 128 + tid + 32] = __fadd_rn(__fmul_rn(x2, c), __fmul_rn(x1, s));
    } else if (tid >= 64) {
        g_kidx[(size_t)t * 128 + tid] = x[tid];
    }
}

// ---------------- indexer scores: grid (4 slices, T rows), longest rows first ----------------
#define SC_SLICES 4
__global__ __launch_bounds__(256) void scores_kernel() {
    int t = (T - 1) - blockIdx.y;
    int slice = blockIdx.x;
    __shared__ float qs[32 * 129];
    __shared__ float ks[32 * 129];
    __shared__ float ws[32];
    __shared__ float lg[32][33];
    int tid = threadIdx.x;
    for (int i = tid; i < 4096; i += 256) {
        int hh = i >> 7, dd = i & 127;
        qs[hh * 129 + dd] = g_qidx[(size_t)t * 4096 + i];
    }
    if (tid < 32) ws[tid] = g_widx[t * 32 + tid];
    int ntile = t / 32 + 1;
    int jl = (tid & 15) * 2;
    int hl = (tid >> 4) * 2;
    for (int jt = slice; jt < ntile; jt += SC_SLICES) {
        int jbase = jt * 32;
        __syncthreads();
        for (int i = tid; i < 4096; i += 256) {
            int jj = i >> 7, dd = i & 127;
            ks[jj * 129 + dd] = g_kidx[(size_t)jbase * 128 + i];
        }
        __syncthreads();
        float a00 = 0.f, a01 = 0.f, a10 = 0.f, a11 = 0.f;
        const float* q0 = &qs[hl * 129];
        const float* q1 = &qs[(hl + 1) * 129];
        const float* k0 = &ks[jl * 129];
        const float* k1 = &ks[(jl + 1) * 129];
#pragma unroll 8
        for (int d = 0; d < 128; d++) {
            float kv0 = k0[d], kv1 = k1[d];
            float qv0 = q0[d], qv1 = q1[d];
            a00 = __fmaf_rn(qv0, kv0, a00); a01 = __fmaf_rn(qv0, kv1, a01);
            a10 = __fmaf_rn(qv1, kv0, a10); a11 = __fmaf_rn(qv1, kv1, a11);
        }
        lg[hl][jl]         = fmaxf(__fmul_rn(a00, ISCALE), 0.f);
        lg[hl][jl + 1]     = fmaxf(__fmul_rn(a01, ISCALE), 0.f);
        lg[hl + 1][jl]     = fmaxf(__fmul_rn(a10, ISCALE), 0.f);
        lg[hl + 1][jl + 1] = fmaxf(__fmul_rn(a11, ISCALE), 0.f);
        __syncthreads();
        if (tid < 32) {
            int j = jbase + tid;
            float s = 0.f;
#pragma unroll
            for (int h = 0; h < 32; h++)
                s = __fmaf_rn(ws[h], lg[h][tid], s);
            g_scores[(size_t)t * T + j] = (j <= t) ? s : -INFINITY;
        }
    }
    for (int j = ntile * 32 + slice * 256 + tid; j < T; j += SC_SLICES * 256)
        g_scores[(size_t)t * T + j] = -INFINITY;
}

// ---------------- per-row top-512: quick path for t<=510, bitonic sort otherwise ----------------
__global__ __launch_bounds__(1024) void topk_kernel() {
    int t = blockIdx.x, tid = threadIdx.x;
    if (t <= TOPK - 2) {
        // all causal keys selected (t+1 finite scores <= 512); -inf picks masked by & causal
        int cnt = t + 1;
        if (tid == 0) g_selcnt[t] = cnt;
        for (int k = tid; k < cnt; k += 1024) g_selidx[t * TOPK + k] = k;
        return;
    }
    __shared__ unsigned long long keys[2048];
    for (int i = tid; i < 2048; i += 1024) {
        float s = g_scores[(size_t)t * T + i];
        unsigned u = __float_as_uint(s);
        u = (u & 0x80000000u) ? ~u : (u | 0x80000000u);
        keys[i] = ((unsigned long long)u << 32) | (unsigned)(2047 - i);
    }
    __syncthreads();
    for (int k = 2; k <= 2048; k <<= 1) {
        for (int j = k >> 1; j > 0; j >>= 1) {
            for (int i = tid; i < 2048; i += 1024) {
                int ixj = i ^ j;
                if (ixj > i) {
                    unsigned long long a = keys[i], b = keys[ixj];
                    bool desc = ((i & k) == 0);
                    if (desc ? (a < b) : (a > b)) { keys[i] = b; keys[ixj] = a; }
                }
            }
            __syncthreads();
        }
    }
    if (tid == 0) g_selcnt[t] = TOPK;
    if (tid < TOPK) {
        g_selidx[t * TOPK + tid] = 2047 - (int)(keys[tid] & 0xFFFFFFFFu);
    }
}

// ---------------- gathered sparse attention (R6-proven layout: block per (t,h)) ----------------
__global__ __launch_bounds__(128) void attn_kernel() {
    int h = blockIdx.x, t = blockIdx.y;
    int tid = threadIdx.x;  // 128
    __shared__ float qn[128];
    __shared__ float qp[64];
    __shared__ float logit[TOPK];
    __shared__ int   sel[TOPK];
    __shared__ float red[128];
    int cnt = g_selcnt[t];
    qn[tid] = g_q[(size_t)t * 3072 + h * 192 + tid];
    if (tid < 64) qp[tid] = g_q[(size_t)t * 3072 + h * 192 + 128 + tid];
    for (int k = tid; k < cnt; k += 128) sel[k] = g_selidx[t * TOPK + k];
    __syncthreads();

    float lmax = -INFINITY;
    for (int k = tid; k < cnt; k += 128) {
        int j = sel[k];
        const float4* kn4 = (const float4*)(g_kv + (size_t)j * 4096 + h * 256);
        float s1 = 0.f;
#pragma unroll
        for (int d4 = 0; d4 < 32; d4++) {
            float4 kv = kn4[d4];
            s1 = __fmaf_rn(qn[4 * d4 + 0], kv.x, s1);
            s1 = __fmaf_rn(qn[4 * d4 + 1], kv.y, s1);
            s1 = __fmaf_rn(qn[4 * d4 + 2], kv.z, s1);
            s1 = __fmaf_rn(qn[4 * d4 + 3], kv.w, s1);
        }
        const float4* kp4 = (const float4*)(g_kpe + (size_t)j * 64);
        float s2 = 0.f;
#pragma unroll
        for (int d4 = 0; d4 < 16; d4++) {
            float4 kv = kp4[d4];
            s2 = __fmaf_rn(qp[4 * d4 + 0], kv.x, s2);
            s2 = __fmaf_rn(qp[4 * d4 + 1], kv.y, s2);
            s2 = __fmaf_rn(qp[4 * d4 + 2], kv.z, s2);
            s2 = __fmaf_rn(qp[4 * d4 + 3], kv.w, s2);
        }
        float s = __fmul_rn(__fadd_rn(s1, s2), SCALE);
        logit[k] = s;
        lmax = fmaxf(lmax, s);
    }
    red[tid] = lmax; __syncthreads();
    for (int o = 64; o; o >>= 1) { if (tid < o) red[tid] = fmaxf(red[tid], red[tid + o]); __syncthreads(); }
    float m = red[0]; __syncthreads();
    float lsum = 0.f;
    for (int k = tid; k < cnt; k += 128) {
        float p = (float)exp((double)__fsub_rn(logit[k], m));
        logit[k] = p;
        lsum += p;
    }
    red[tid] = lsum; __syncthreads();
    for (int o = 64; o; o >>= 1) { if (tid < o) red[tid] += red[tid + o]; __syncthreads(); }
    float denom = red[0];
    __syncthreads();
    for (int k = tid; k < cnt; k += 128) logit[k] = __fdiv_rn(logit[k], denom);
    __syncthreads();

    float acc = 0.f;
    for (int k = 0; k < cnt; k++) {
        int j = sel[k];
        acc = __fmaf_rn(logit[k], g_kv[(size_t)j * 4096 + h * 256 + 128 + tid], acc);
    }
    g_obuf[(size_t)t * 2048 + h * 128 + tid] = acc;
}

// ---------------- launch ----------------
extern "C" void kernel_launch(void* const* d_in, const int* in_sizes, int n_in,
                              void* d_out, int out_size) {
    const int*   positions = (const int*)d_in[0];
    const float* hidden    = (const float*)d_in[1];
    const float* q_c       = (const float*)d_in[2];
    const float* kv_c      = (const float*)d_in[3];
    const float* k_pe      = (const float*)d_in[4];
    const float* q_a_ln_w  = (const float*)d_in[5];
    const float* kv_a_ln_w = (const float*)d_in[6];
    const float* Wq_b      = (const float*)d_in[7];
    const float* Wkv_b     = (const float*)d_in[8];
    const float* Wo        = (const float*)d_in[9];
    const float* Wiq       = (const float*)d_in[10];
    const float* Wik       = (const float*)d_in[11];
    const float* ik_gamma  = (const float*)d_in[12];
    const float* ik_beta   = (const float*)d_in[13];
    const float* Ww        = (const float*)d_in[14];
    float* out = (float*)d_out;

    float* p_qcn;     cudaGetSymbolAddress((void**)&p_qcn, g_qcn);
    float* p_kvn;     cudaGetSymbolAddress((void**)&p_kvn, g_kvn);
    float* p_q;       cudaGetSymbolAddress((void**)&p_q, g_q);
    float* p_kv;      cudaGetSymbolAddress((void**)&p_kv, g_kv);
    float* p_qidx;    cudaGetSymbolAddress((void**)&p_qidx, g_qidx);
    float* p_kidxraw; cudaGetSymbolAddress((void**)&p_kidxraw, g_kidxraw);
    float* p_widx;    cudaGetSymbolAddress((void**)&p_widx, g_widx);
    float* p_obuf;    cudaGetSymbolAddress((void**)&p_obuf, g_obuf);

    rope_table_kernel<<<T, 32>>>(positions);
    rmsnorm_kernel<<<T, 256>>>(q_c, q_a_ln_w, p_qcn, QLR);
    rmsnorm_kernel<<<T, 256>>>(kv_c, kv_a_ln_w, p_kvn, KVLR);

    sgemm_kernel<<<dim3(3072 / 128, T / 128), 256>>>(p_qcn, Wq_b, p_q, T, 3072, QLR, 1.f);
    sgemm_kernel<<<dim3(4096 / 128, T / 128), 256>>>(p_kvn, Wkv_b, p_kv, T, 4096, KVLR, 1.f);
    sgemm_kernel<<<dim3(4096 / 128, T / 128), 256>>>(p_qcn, Wiq, p_qidx, T, 4096, QLR, 1.f);
    skinny_sgemm_kernel<<<dim3(1, T / 8), 256>>>(hidden, Wik, p_kidxraw, T, 128, HID, 1.f);
    skinny_sgemm_kernel<<<dim3(1, T / 8), 256>>>(hidden, Ww, p_widx, T, 32, HID, WSCALE);

    rope_q_kernel<<<T * H, 32>>>();
    rope_kpe_kernel<<<T, 32>>>(k_pe);
    rope_qidx_kernel<<<T * IH, 32>>>();
    kidx_kernel<<<T, 128>>>(ik_gamma, ik_beta);

    scores_kernel<<<dim3(SC_SLICES, T), 256>>>();
    topk_kernel<<<T, 1024>>>();
    attn_kernel<<<dim3(H, T), 128>>>();

    sgemm_kernel<<<dim3(HID / 128, T / 128), 256>>>(p_obuf, Wo, out, T, HID, 2048, 1.f);
}